// round 3
// baseline (speedup 1.0000x reference)
#include <cuda_runtime.h>
#include <math.h>

// out[b,d] = iw[A-1,d] * (sum_a spw[a]*hs[b,idx[a],d]) / (sum_a spw[a])
// Anchors are always a prefix of the constant set {0,1,2,5} (A<=4), with
// counts[a] = Fib(position-idx[a]+1). ALL load addresses are independent of
// `position` (anchor rows are constants; all 4 candidate iw rows loaded and
// selected later), so every DRAM access issues at kernel start and overlaps
// in a single memory round trip. `position` only gates the scalar weights.

__device__ __forceinline__ float softplus_f(float x) {
    // logaddexp(x, 0), numerically stable
    return fmaxf(x, 0.0f) + log1pf(expf(-fabsf(x)));
}

__global__ void __launch_bounds__(128, 1)
fla_kernel(const float* __restrict__ hs,
           const float* __restrict__ iw,
           const float* __restrict__ w1,
           const float* __restrict__ b1,
           const float* __restrict__ w2,
           const float* __restrict__ b2,
           const int* __restrict__ pos_p,
           float* __restrict__ out,
           int B, int S, int D) {
    const int tid  = blockIdx.x * blockDim.x + threadIdx.x;
    const int lane = threadIdx.x & 31;
    const int a    = lane >> 3;   // anchor group 0..3
    const int s    = lane & 7;    // hidden-slice 0..7

    const int SP0 = 0, SP1 = 1, SP2 = 2, SP3 = 5;

    // ================= issue EVERY load up front (no position dependence) ===
    const int position = __ldg(pos_p);

    const int D4 = D >> 2;
    const int b_ = tid / D4;
    const int d4 = tid - b_ * D4;
    const bool active = (tid < B * D4);

    float4 z = make_float4(0.f, 0.f, 0.f, 0.f);
    float4 v0 = z, v1 = z, v2 = z, v3 = z;
    float4 g0 = z, g1 = z, g2 = z, g3 = z;
    if (active) {
        const float4* base = reinterpret_cast<const float4*>(hs + (size_t)b_ * S * D) + d4;
        // predicates depend only on S (kernel arg) -> issue immediately
        v0 = __ldg(base + (size_t)SP0 * D4);
        if (SP1 < S) v1 = __ldg(base + (size_t)SP1 * D4);
        if (SP2 < S) v2 = __ldg(base + (size_t)SP2 * D4);
        if (SP3 < S) v3 = __ldg(base + (size_t)SP3 * D4);
        const float4* iwv = reinterpret_cast<const float4*>(iw) + d4;
        g0 = __ldg(iwv);
        g1 = __ldg(iwv + D4);
        g2 = __ldg(iwv + 2 * D4);
        g3 = __ldg(iwv + 3 * D4);
    }

    // MLP weight slices (also position-independent)
    const float4* w1v = reinterpret_cast<const float4*>(w1);
    const float4* b1v = reinterpret_cast<const float4*>(b1);
    const float4* w2v = reinterpret_cast<const float4*>(w2);
    const float4 w1a = __ldg(&w1v[2 * s]);
    const float4 w1b = __ldg(&w1v[2 * s + 1]);
    const float4 b1a = __ldg(&b1v[2 * s]);
    const float4 b1b = __ldg(&b1v[2 * s + 1]);
    const float4 w2a = __ldg(&w2v[2 * s]);
    const float4 w2b = __ldg(&w2v[2 * s + 1]);
    const float  b2s = __ldg(b2);

    // ================= scalar logic (under load latency) =====================
    int A = 0;
    if (position >= 1 && position < 13) {
        A = (SP0 < position && SP0 < S)
          + (SP1 < position && SP1 < S)
          + (SP2 < position && SP2 < S)
          + (SP3 < position && SP3 < S);
    }

    if (A == 0) {   // reference returns zeros
        const int total = B * D;
        for (int i = tid; i < total; i += gridDim.x * blockDim.x) out[i] = 0.0f;
        return;
    }

    // counts[a] = Fib(position - sp + 1); fibt[k] for k = position - sp
    const float fibt[13] = {0.f,1.f,2.f,3.f,5.f,8.f,13.f,21.f,34.f,55.f,89.f,144.f,233.f};
    const int spv[4] = {SP0, SP1, SP2, SP3};
    int k = position - spv[a];
    k = (k < 0) ? 0 : (k > 12 ? 12 : k);
    const float c = fibt[k];

    // MLP partial: anchor a, hidden units [8s, 8s+8)
    float h0 = fmaxf(fmaf(c, w1a.x, b1a.x), 0.f);
    float h1 = fmaxf(fmaf(c, w1a.y, b1a.y), 0.f);
    float h2 = fmaxf(fmaf(c, w1a.z, b1a.z), 0.f);
    float h3 = fmaxf(fmaf(c, w1a.w, b1a.w), 0.f);
    float h4 = fmaxf(fmaf(c, w1b.x, b1b.x), 0.f);
    float h5 = fmaxf(fmaf(c, w1b.y, b1b.y), 0.f);
    float h6 = fmaxf(fmaf(c, w1b.z, b1b.z), 0.f);
    float h7 = fmaxf(fmaf(c, w1b.w, b1b.w), 0.f);
    float q0 = h0 * w2a.x + h1 * w2a.y;
    float q1 = h2 * w2a.z + h3 * w2a.w;
    float q2 = h4 * w2b.x + h5 * w2b.y;
    float q3 = h6 * w2b.z + h7 * w2b.w;
    float p  = (q0 + q1) + (q2 + q3);

    p += __shfl_xor_sync(0xffffffffu, p, 1);
    p += __shfl_xor_sync(0xffffffffu, p, 2);
    p += __shfl_xor_sync(0xffffffffu, p, 4);

    float spw = (a < A) ? softplus_f(p + b2s) : 0.0f;

    float ssum = spw;
    ssum += __shfl_xor_sync(0xffffffffu, ssum, 8);
    ssum += __shfl_xor_sync(0xffffffffu, ssum, 16);

    const float wa0 = __shfl_sync(0xffffffffu, spw, 0);
    const float wa1 = __shfl_sync(0xffffffffu, spw, 8);
    const float wa2 = __shfl_sync(0xffffffffu, spw, 16);
    const float wa3 = __shfl_sync(0xffffffffu, spw, 24);
    const float inv = __frcp_rn(ssum);

    if (active) {
        // select interference row for this A (1..4 -> rows 0..3)
        float4 g = (A == 1) ? g0 : (A == 2) ? g1 : (A == 3) ? g2 : g3;

        float4 acc;
        acc.x = wa0 * v0.x; acc.y = wa0 * v0.y; acc.z = wa0 * v0.z; acc.w = wa0 * v0.w;
        acc.x = fmaf(wa1, v1.x, acc.x); acc.y = fmaf(wa1, v1.y, acc.y);
        acc.z = fmaf(wa1, v1.z, acc.z); acc.w = fmaf(wa1, v1.w, acc.w);
        acc.x = fmaf(wa2, v2.x, acc.x); acc.y = fmaf(wa2, v2.y, acc.y);
        acc.z = fmaf(wa2, v2.z, acc.z); acc.w = fmaf(wa2, v2.w, acc.w);
        acc.x = fmaf(wa3, v3.x, acc.x); acc.y = fmaf(wa3, v3.y, acc.y);
        acc.z = fmaf(wa3, v3.z, acc.z); acc.w = fmaf(wa3, v3.w, acc.w);
        const float sx = g.x * inv, sy = g.y * inv, sz = g.z * inv, sw = g.w * inv;
        reinterpret_cast<float4*>(out)[tid] =
            make_float4(acc.x * sx, acc.y * sy, acc.z * sz, acc.w * sw);
    }
}

// Fallback for D not divisible by 4 (not hit for this problem's shapes).
__global__ void fla_kernel_scalar(const float* __restrict__ hs,
                                  const float* __restrict__ iw,
                                  const float* __restrict__ w1,
                                  const float* __restrict__ b1,
                                  const float* __restrict__ w2,
                                  const float* __restrict__ b2,
                                  const int* __restrict__ pos_p,
                                  float* __restrict__ out,
                                  int B, int S, int D) {
    const int position = __ldg(pos_p);
    const int SPV[4] = {0, 1, 2, 5};
    int A = 0;
    if (position >= 1 && position < 13)
        for (int t = 0; t < 4; t++) A += (SPV[t] < position && SPV[t] < S);
    const int total = B * D;
    const int tid = blockIdx.x * blockDim.x + threadIdx.x;
    if (A == 0) {
        for (int i = tid; i < total; i += gridDim.x * blockDim.x) out[i] = 0.0f;
        return;
    }
    const float fibt[13] = {0.f,1.f,2.f,3.f,5.f,8.f,13.f,21.f,34.f,55.f,89.f,144.f,233.f};
    float spw[4], ssum = 0.f;
    for (int t = 0; t < 4; t++) {
        if (t < A) {
            float c = fibt[position - SPV[t]];
            float acc = 0.f;
            for (int j = 0; j < 64; j++)
                acc = fmaf(fmaxf(fmaf(c, w1[j], b1[j]), 0.f), w2[j], acc);
            float x = acc + b2[0];
            spw[t] = fmaxf(x, 0.f) + log1pf(expf(-fabsf(x)));
        } else spw[t] = 0.f;
        ssum += spw[t];
    }
    const float inv = 1.0f / ssum;
    const float* iwr = iw + (size_t)(A - 1) * D;
    for (int i = tid; i < total; i += gridDim.x * blockDim.x) {
        int b = i / D, d = i - b * D;
        float acc = 0.f;
        for (int t = 0; t < A; t++)
            acc = fmaf(spw[t], hs[(size_t)b * S * D + (size_t)SPV[t] * D + d], acc);
        out[i] = acc * iwr[d] * inv;
    }
}

extern "C" void kernel_launch(void* const* d_in, const int* in_sizes, int n_in,
                              void* d_out, int out_size) {
    const float* hs  = (const float*)d_in[0];  // (B, S, D)
    const float* iw  = (const float*)d_in[1];  // (10, D)
    const float* w1  = (const float*)d_in[2];  // (64, 1)
    const float* b1  = (const float*)d_in[3];  // (64,)
    const float* w2  = (const float*)d_in[4];  // (1, 64)
    const float* b2  = (const float*)d_in[5];  // (1,)
    const int*   pos = (const int*)d_in[6];    // scalar

    const int D = in_sizes[1] / 10;
    const int B = out_size / D;
    const int S = in_sizes[0] / (B * D);
    float* out = (float*)d_out;

    if ((D & 3) == 0) {
        const int total4 = B * (D >> 2);
        const int blocks = (total4 + 127) / 128;
        fla_kernel<<<blocks, 128>>>(hs, iw, w1, b1, w2, b2, pos, out, B, S, D);
    } else {
        const int total = B * D;
        int blocks = (total + 255) / 256;
        if (blocks > 148) blocks = 148;
        fla_kernel_scalar<<<blocks, 256>>>(hs, iw, w1, b1, w2, b2, pos, out, B, S, D);
    }
}